// round 1
// baseline (speedup 1.0000x reference)
#include <cuda_runtime.h>
#include <cuda_bf16.h>
#include <math.h>

#define NN 100000
#define EE 1600000
#define DDIM 64
#define GGR 2000

// Scratch (allocation-free rule: __device__ globals)
__device__ float g_x[NN * DDIM];     // current node features
__device__ float g_h[NN * DDIM];     // pre-MLP features (init + scatter target)
__device__ float g_gate[NN];         // attention gate logits

// ---------------------------------------------------------------------------
// h = (1 + eps[l]) * x   (vectorized float4)
// ---------------------------------------------------------------------------
__global__ void k_init(float* __restrict__ H, const float* __restrict__ X,
                       const float* __restrict__ eps, int l, int total4) {
    int i = blockIdx.x * blockDim.x + threadIdx.x;
    if (i >= total4) return;
    float s = 1.0f + eps[l];
    float4 v = ((const float4*)X)[i];
    v.x *= s; v.y *= s; v.z *= s; v.w *= s;
    ((float4*)H)[i] = v;
}

// ---------------------------------------------------------------------------
// scatter-add: H[dst] += X[src] for each edge, 16 threads/edge, red.v4.f32
// ---------------------------------------------------------------------------
__global__ void k_scatter(float* __restrict__ H, const float* __restrict__ X,
                          const int* __restrict__ src, const int* __restrict__ dst,
                          int nEdges) {
    long long tid = (long long)blockIdx.x * blockDim.x + threadIdx.x;
    int e = (int)(tid >> 4);
    int j = (int)(tid & 15);
    if (e >= nEdges) return;
    int s = __ldg(&src[e]);
    int d = __ldg(&dst[e]);
    float4 v = *(const float4*)(X + (size_t)s * DDIM + j * 4);
    float* p = H + (size_t)d * DDIM + j * 4;
    asm volatile("red.global.add.v4.f32 [%0], {%1, %2, %3, %4};"
                 :: "l"(p), "f"(v.x), "f"(v.y), "f"(v.z), "f"(v.w) : "memory");
}

// ---------------------------------------------------------------------------
// Fused MLP + LayerNorm: out = LN( silu(H@W1+b1)@W2 + b2 )
// Block: 256 threads (16x16), tile = 64 nodes x 64 cols, 4x4 per thread.
// ---------------------------------------------------------------------------
__global__ void __launch_bounds__(256) k_mlp(
    const float* __restrict__ H,
    const float* __restrict__ W1, const float* __restrict__ B1,
    const float* __restrict__ W2, const float* __restrict__ B2,
    const float* __restrict__ LG, const float* __restrict__ LB,
    float* __restrict__ O, int n) {
    __shared__ __align__(16) float sW[64 * 64];   // weight tile (W1 then W2)
    __shared__ __align__(16) float sH[64 * 68];   // node tile (h, then silu(t))

    int tid = threadIdx.x;
    int tx = tid & 15, ty = tid >> 4;
    int n0 = blockIdx.x * 64;
    int r0 = ty * 4, c0 = tx * 4;

    // load H tile (zeros beyond n) and W1
    #pragma unroll
    for (int idx = tid * 4; idx < 64 * 64; idx += 256 * 4) {
        int i = idx >> 6, d = idx & 63;
        float4 v = make_float4(0.f, 0.f, 0.f, 0.f);
        if (n0 + i < n) v = *(const float4*)(H + (size_t)(n0 + i) * 64 + d);
        *(float4*)(&sH[i * 68 + d]) = v;
    }
    #pragma unroll
    for (int idx = tid * 4; idx < 4096; idx += 1024)
        *(float4*)(&sW[idx]) = *(const float4*)(W1 + idx);
    __syncthreads();

    // GEMM1: t = h @ W1
    float acc[4][4];
    #pragma unroll
    for (int j = 0; j < 4; j++)
        #pragma unroll
        for (int i = 0; i < 4; i++) acc[j][i] = 0.f;
    #pragma unroll 8
    for (int k = 0; k < 64; k++) {
        float a0 = sH[(r0 + 0) * 68 + k];
        float a1 = sH[(r0 + 1) * 68 + k];
        float a2 = sH[(r0 + 2) * 68 + k];
        float a3 = sH[(r0 + 3) * 68 + k];
        float4 b = *(float4*)(&sW[k * 64 + c0]);
        acc[0][0] += a0 * b.x; acc[0][1] += a0 * b.y; acc[0][2] += a0 * b.z; acc[0][3] += a0 * b.w;
        acc[1][0] += a1 * b.x; acc[1][1] += a1 * b.y; acc[1][2] += a1 * b.z; acc[1][3] += a1 * b.w;
        acc[2][0] += a2 * b.x; acc[2][1] += a2 * b.y; acc[2][2] += a2 * b.z; acc[2][3] += a2 * b.w;
        acc[3][0] += a3 * b.x; acc[3][1] += a3 * b.y; acc[3][2] += a3 * b.z; acc[3][3] += a3 * b.w;
    }
    float4 bb1 = *(const float4*)(B1 + c0);
    float bias1[4] = {bb1.x, bb1.y, bb1.z, bb1.w};
    __syncthreads();  // everyone done reading sH/sW

    // silu + store back into sH ; reload sW with W2
    #pragma unroll
    for (int j = 0; j < 4; j++)
        #pragma unroll
        for (int i = 0; i < 4; i++) {
            float t = acc[j][i] + bias1[i];
            float sil = t / (1.f + __expf(-t));
            sH[(r0 + j) * 68 + c0 + i] = sil;
        }
    #pragma unroll
    for (int idx = tid * 4; idx < 4096; idx += 1024)
        *(float4*)(&sW[idx]) = *(const float4*)(W2 + idx);
    __syncthreads();

    // GEMM2: u = silu(t) @ W2
    float u[4][4];
    #pragma unroll
    for (int j = 0; j < 4; j++)
        #pragma unroll
        for (int i = 0; i < 4; i++) u[j][i] = 0.f;
    #pragma unroll 8
    for (int k = 0; k < 64; k++) {
        float a0 = sH[(r0 + 0) * 68 + k];
        float a1 = sH[(r0 + 1) * 68 + k];
        float a2 = sH[(r0 + 2) * 68 + k];
        float a3 = sH[(r0 + 3) * 68 + k];
        float4 b = *(float4*)(&sW[k * 64 + c0]);
        u[0][0] += a0 * b.x; u[0][1] += a0 * b.y; u[0][2] += a0 * b.z; u[0][3] += a0 * b.w;
        u[1][0] += a1 * b.x; u[1][1] += a1 * b.y; u[1][2] += a1 * b.z; u[1][3] += a1 * b.w;
        u[2][0] += a2 * b.x; u[2][1] += a2 * b.y; u[2][2] += a2 * b.z; u[2][3] += a2 * b.w;
        u[3][0] += a3 * b.x; u[3][1] += a3 * b.y; u[3][2] += a3 * b.z; u[3][3] += a3 * b.w;
    }
    float4 bb2 = *(const float4*)(B2 + c0);
    float bias2[4] = {bb2.x, bb2.y, bb2.z, bb2.w};
    #pragma unroll
    for (int j = 0; j < 4; j++)
        #pragma unroll
        for (int i = 0; i < 4; i++) u[j][i] += bias2[i];

    // LayerNorm per row: row r0+j spread across 16 tx-lanes (one half-warp)
    float4 g4 = *(const float4*)(LG + c0);
    float4 lb4 = *(const float4*)(LB + c0);
    #pragma unroll
    for (int j = 0; j < 4; j++) {
        float s = u[j][0] + u[j][1] + u[j][2] + u[j][3];
        #pragma unroll
        for (int o = 1; o < 16; o <<= 1) s += __shfl_xor_sync(0xffffffffu, s, o);
        float mu = s * (1.f / 64.f);
        float d0 = u[j][0] - mu, d1 = u[j][1] - mu, d2 = u[j][2] - mu, d3 = u[j][3] - mu;
        float q = d0 * d0 + d1 * d1 + d2 * d2 + d3 * d3;
        #pragma unroll
        for (int o = 1; o < 16; o <<= 1) q += __shfl_xor_sync(0xffffffffu, q, o);
        float rstd = rsqrtf(q * (1.f / 64.f) + 1e-5f);
        int row = n0 + r0 + j;
        if (row < n) {
            float4 o4;
            o4.x = d0 * rstd * g4.x + lb4.x;
            o4.y = d1 * rstd * g4.y + lb4.y;
            o4.z = d2 * rstd * g4.z + lb4.z;
            o4.w = d3 * rstd * g4.w + lb4.w;
            *(float4*)(O + (size_t)row * 64 + c0) = o4;
        }
    }
}

// ---------------------------------------------------------------------------
// gate = silu(x @ gw1 + gb1) @ gw2 + gb2    (one warp per node)
// ---------------------------------------------------------------------------
__global__ void __launch_bounds__(256) k_gate(
    const float* __restrict__ X,
    const float* __restrict__ GW1, const float* __restrict__ GB1,
    const float* __restrict__ GW2, const float* __restrict__ GB2,
    float* __restrict__ gate, int n) {
    __shared__ float sg[64 * 32];
    int tid = threadIdx.x;
    for (int i = tid; i < 64 * 32; i += 256) sg[i] = GW1[i];
    __syncthreads();
    int lane = tid & 31, w = tid >> 5;
    int node = blockIdx.x * 8 + w;
    if (node >= n) return;
    float t = GB1[lane];
    const float* xr = X + (size_t)node * 64;
    #pragma unroll
    for (int k = 0; k < 64; k++) t += xr[k] * sg[k * 32 + lane];
    float sil = t / (1.f + __expf(-t));
    float v = sil * GW2[lane];
    #pragma unroll
    for (int o = 16; o > 0; o >>= 1) v += __shfl_xor_sync(0xffffffffu, v, o);
    if (lane == 0) gate[node] = v + GB2[0];
}

// ---------------------------------------------------------------------------
// Per-graph softmax attention pool. batch is sorted -> binary-search segment.
// One block (64 threads) per graph; no atomics.
// ---------------------------------------------------------------------------
__global__ void k_pool(const float* __restrict__ X, const float* __restrict__ gate,
                       const int* __restrict__ batch, float* __restrict__ out, int n) {
    int g = blockIdx.x;
    int tid = threadIdx.x;  // 64 threads

    int lo = 0, hi = n;
    while (lo < hi) { int mid = (lo + hi) >> 1; if (batch[mid] < g) lo = mid + 1; else hi = mid; }
    int start = lo;
    lo = start; hi = n;
    while (lo < hi) { int mid = (lo + hi) >> 1; if (batch[mid] < g + 1) lo = mid + 1; else hi = mid; }
    int end = lo;

    if (start >= end) { out[(size_t)g * 64 + tid] = 0.f; return; }

    __shared__ float wred[2];
    // segment max
    float m = -3.402823e38f;
    for (int i = start + tid; i < end; i += 64) m = fmaxf(m, gate[i]);
    #pragma unroll
    for (int o = 16; o > 0; o >>= 1) m = fmaxf(m, __shfl_xor_sync(0xffffffffu, m, o));
    if ((tid & 31) == 0) wred[tid >> 5] = m;
    __syncthreads();
    m = fmaxf(wred[0], wred[1]);
    __syncthreads();
    // denom
    float s = 0.f;
    for (int i = start + tid; i < end; i += 64) s += __expf(gate[i] - m);
    #pragma unroll
    for (int o = 16; o > 0; o >>= 1) s += __shfl_xor_sync(0xffffffffu, s, o);
    if ((tid & 31) == 0) wred[tid >> 5] = s;
    __syncthreads();
    float inv = 1.f / (wred[0] + wred[1]);

    // weighted sum: thread `tid` owns feature dim `tid`
    float acc = 0.f;
    for (int i = start; i < end; i++) {
        float w = __expf(gate[i] - m);
        acc += w * X[(size_t)i * 64 + tid];
    }
    out[(size_t)g * 64 + tid] = acc * inv;
}

// ---------------------------------------------------------------------------
extern "C" void kernel_launch(void* const* d_in, const int* in_sizes, int n_in,
                              void* d_out, int out_size) {
    const float* x   = (const float*)d_in[0];
    const int*   ei  = (const int*)d_in[1];
    const int*   bat = (const int*)d_in[2];
    const float* W1  = (const float*)d_in[3];
    const float* b1  = (const float*)d_in[4];
    const float* W2  = (const float*)d_in[5];
    const float* b2  = (const float*)d_in[6];
    const float* eps = (const float*)d_in[7];
    const float* lng = (const float*)d_in[8];
    const float* lnb = (const float*)d_in[9];
    const float* gw1 = (const float*)d_in[10];
    const float* gb1 = (const float*)d_in[11];
    const float* gw2 = (const float*)d_in[12];
    const float* gb2 = (const float*)d_in[13];
    float* out = (float*)d_out;

    int n = in_sizes[0] / DDIM;
    int e = in_sizes[1] / 2;
    int g = out_size / DDIM;
    const int* src = ei;
    const int* dst = ei + e;

    float *gx, *gh, *ggate;
    cudaGetSymbolAddress((void**)&gx, g_x);
    cudaGetSymbolAddress((void**)&gh, g_h);
    cudaGetSymbolAddress((void**)&ggate, g_gate);

    int total4 = n * (DDIM / 4);
    for (int l = 0; l < 3; l++) {
        const float* xin = (l == 0) ? x : gx;
        k_init<<<(total4 + 255) / 256, 256>>>(gh, xin, eps, l, total4);
        long long sthreads = (long long)e * 16;
        k_scatter<<<(unsigned)((sthreads + 255) / 256), 256>>>(gh, xin, src, dst, e);
        k_mlp<<<(n + 63) / 64, 256>>>(gh, W1 + l * 4096, b1 + l * 64,
                                      W2 + l * 4096, b2 + l * 64,
                                      lng + l * 64, lnb + l * 64, gx, n);
    }
    k_gate<<<(n + 7) / 8, 256>>>(gx, gw1, gb1, gw2, gb2, ggate, n);
    k_pool<<<g, 64>>>(gx, ggate, bat, out, n);
}

// round 2
// speedup vs baseline: 1.3684x; 1.3684x over previous
#include <cuda_runtime.h>
#include <cuda_bf16.h>
#include <math.h>

#define NN 100000
#define EE 1600000
#define DDIM 64
#define GGR 2000

// Scratch (allocation-free rule: __device__ globals)
__device__ float g_a[NN * DDIM];     // node features (ping)
__device__ float g_b[NN * DDIM];     // node features (pong)
__device__ float g_gate[NN];         // attention gate logits
__device__ int   g_deg[NN];
__device__ int   g_rs[NN];           // CSR row starts
__device__ int   g_cur[NN];          // fill cursors
__device__ int   g_csr[EE];          // src indices grouped by dst
__device__ int   g_total;            // row-range allocator

// ---------------------------------------------------------------------------
// f32x2 packed-FMA helpers (FFMA2 — ptxas won't auto-fuse; PTX only)
// ---------------------------------------------------------------------------
typedef unsigned long long u64;
__device__ __forceinline__ u64 pack2(float lo, float hi) {
    u64 r; asm("mov.b64 %0, {%1, %2};" : "=l"(r) : "f"(lo), "f"(hi)); return r;
}
__device__ __forceinline__ u64 dup2(float a) {
    u64 r; asm("mov.b64 %0, {%1, %1};" : "=l"(r) : "f"(a)); return r;
}
__device__ __forceinline__ void fma2(u64& d, u64 a, u64 b) {
    asm("fma.rn.f32x2 %0, %1, %2, %0;" : "+l"(d) : "l"(a), "l"(b));
}
__device__ __forceinline__ float2 unpack2(u64 v) {
    float2 f; asm("mov.b64 {%0, %1}, %2;" : "=f"(f.x), "=f"(f.y) : "l"(v)); return f;
}

// ---------------------------------------------------------------------------
// CSR build
// ---------------------------------------------------------------------------
__global__ void k_zero(int* __restrict__ deg, int n) {
    int i = blockIdx.x * blockDim.x + threadIdx.x;
    if (i == 0) g_total = 0;
    if (i < n) deg[i] = 0;
}

__global__ void k_hist(const int* __restrict__ dst, int* __restrict__ deg, int e) {
    int i = blockIdx.x * blockDim.x + threadIdx.x;
    if (i >= e) return;
    atomicAdd(&deg[__ldg(&dst[i])], 1);
}

__global__ void __launch_bounds__(256) k_alloc(
    const int* __restrict__ deg, int* __restrict__ rs, int* __restrict__ cur, int n) {
    __shared__ int sdata[256];
    __shared__ int base;
    int tx = threadIdx.x;
    int i = blockIdx.x * 256 + tx;
    int d = (i < n) ? deg[i] : 0;
    sdata[tx] = d;
    __syncthreads();
    #pragma unroll
    for (int o = 1; o < 256; o <<= 1) {
        int t = (tx >= o) ? sdata[tx - o] : 0;
        __syncthreads();
        sdata[tx] += t;
        __syncthreads();
    }
    int incl = sdata[tx];
    if (tx == 255) base = atomicAdd(&g_total, incl);
    __syncthreads();
    int start = base + incl - d;
    if (i < n) { rs[i] = start; cur[i] = start; }
}

__global__ void k_fill(const int* __restrict__ src, const int* __restrict__ dst,
                       int* __restrict__ cur, int* __restrict__ csr, int e) {
    int i = blockIdx.x * blockDim.x + threadIdx.x;
    if (i >= e) return;
    int d = __ldg(&dst[i]);
    int p = atomicAdd(&cur[d], 1);
    csr[p] = __ldg(&src[i]);
}

// ---------------------------------------------------------------------------
// Fused: gather (GIN aggregate) + MLP + LayerNorm for a 64-node tile.
//   h   = (1+eps)*x[i] + sum_{j in N(i)} x[j]         (warp-per-row gather)
//   out = LN( silu(h@W1+b1)@W2 + b2 )                  (f32x2 register GEMM)
// Block: 256 threads (16x16), 4 rows x 4 cols per thread.
// ---------------------------------------------------------------------------
__global__ void __launch_bounds__(256) k_mlp(
    const float* __restrict__ X,
    const int* __restrict__ deg, const int* __restrict__ rs, const int* __restrict__ csr,
    const float* __restrict__ eps, int l,
    const float* __restrict__ W1, const float* __restrict__ B1,
    const float* __restrict__ W2, const float* __restrict__ B2,
    const float* __restrict__ LG, const float* __restrict__ LB,
    float* __restrict__ O, int n) {
    __shared__ __align__(16) float sW[64 * 64];
    __shared__ __align__(16) float sH[64 * 68];

    int tid = threadIdx.x;
    int tx = tid & 15, ty = tid >> 4;
    int n0 = blockIdx.x * 64;
    int r0 = ty * 4, c0 = tx * 4;

    // W1 -> smem
    #pragma unroll
    for (int idx = tid * 4; idx < 4096; idx += 1024)
        *(float4*)(&sW[idx]) = *(const float4*)(W1 + idx);

    // gather: warp w handles rows w, w+8, ... (lane owns 2 feature dims)
    {
        int lane = tid & 31, w = tid >> 5;
        float s = 1.0f + __ldg(&eps[l]);
        for (int r = w; r < 64; r += 8) {
            int node = n0 + r;
            float2 acc = make_float2(0.f, 0.f);
            if (node < n) {
                acc = ((const float2*)(X + (size_t)node * 64))[lane];
                acc.x *= s; acc.y *= s;
                int start = __ldg(&rs[node]);
                int d = __ldg(&deg[node]);
                for (int t = 0; t < d; t++) {
                    int j = __ldg(&csr[start + t]);
                    float2 v = ((const float2*)(X + (size_t)j * 64))[lane];
                    acc.x += v.x; acc.y += v.y;
                }
            }
            ((float2*)(&sH[r * 68]))[lane] = acc;
        }
    }
    __syncthreads();

    // GEMM1: t = h @ W1  (f32x2 packed)
    u64 acc[4][2];
    #pragma unroll
    for (int j = 0; j < 4; j++) { acc[j][0] = 0ull; acc[j][1] = 0ull; }
    #pragma unroll 8
    for (int k = 0; k < 64; k++) {
        float4 b = *(float4*)(&sW[k * 64 + c0]);
        u64 b01 = pack2(b.x, b.y), b23 = pack2(b.z, b.w);
        #pragma unroll
        for (int j = 0; j < 4; j++) {
            u64 aa = dup2(sH[(r0 + j) * 68 + k]);
            fma2(acc[j][0], aa, b01);
            fma2(acc[j][1], aa, b23);
        }
    }
    float4 bb1 = *(const float4*)(B1 + c0);
    __syncthreads();  // done reading sH/sW

    // silu -> sH ; reload sW with W2
    #pragma unroll
    for (int j = 0; j < 4; j++) {
        float2 t01 = unpack2(acc[j][0]);
        float2 t23 = unpack2(acc[j][1]);
        float t0 = t01.x + bb1.x, t1 = t01.y + bb1.y;
        float t2 = t23.x + bb1.z, t3 = t23.y + bb1.w;
        sH[(r0 + j) * 68 + c0 + 0] = t0 / (1.f + __expf(-t0));
        sH[(r0 + j) * 68 + c0 + 1] = t1 / (1.f + __expf(-t1));
        sH[(r0 + j) * 68 + c0 + 2] = t2 / (1.f + __expf(-t2));
        sH[(r0 + j) * 68 + c0 + 3] = t3 / (1.f + __expf(-t3));
    }
    #pragma unroll
    for (int idx = tid * 4; idx < 4096; idx += 1024)
        *(float4*)(&sW[idx]) = *(const float4*)(W2 + idx);
    __syncthreads();

    // GEMM2: u = silu(t) @ W2  (f32x2 packed)
    u64 uacc[4][2];
    #pragma unroll
    for (int j = 0; j < 4; j++) { uacc[j][0] = 0ull; uacc[j][1] = 0ull; }
    #pragma unroll 8
    for (int k = 0; k < 64; k++) {
        float4 b = *(float4*)(&sW[k * 64 + c0]);
        u64 b01 = pack2(b.x, b.y), b23 = pack2(b.z, b.w);
        #pragma unroll
        for (int j = 0; j < 4; j++) {
            u64 aa = dup2(sH[(r0 + j) * 68 + k]);
            fma2(uacc[j][0], aa, b01);
            fma2(uacc[j][1], aa, b23);
        }
    }
    float4 bb2 = *(const float4*)(B2 + c0);

    // LayerNorm per row (row spread across 16 tx-lanes of a half-warp)
    float4 g4 = *(const float4*)(LG + c0);
    float4 lb4 = *(const float4*)(LB + c0);
    #pragma unroll
    for (int j = 0; j < 4; j++) {
        float2 u01 = unpack2(uacc[j][0]);
        float2 u23 = unpack2(uacc[j][1]);
        float u0 = u01.x + bb2.x, u1 = u01.y + bb2.y;
        float u2 = u23.x + bb2.z, u3 = u23.y + bb2.w;
        float s = u0 + u1 + u2 + u3;
        #pragma unroll
        for (int o = 1; o < 16; o <<= 1) s += __shfl_xor_sync(0xffffffffu, s, o);
        float mu = s * (1.f / 64.f);
        float d0 = u0 - mu, d1 = u1 - mu, d2 = u2 - mu, d3 = u3 - mu;
        float q = d0 * d0 + d1 * d1 + d2 * d2 + d3 * d3;
        #pragma unroll
        for (int o = 1; o < 16; o <<= 1) q += __shfl_xor_sync(0xffffffffu, q, o);
        float rstd = rsqrtf(q * (1.f / 64.f) + 1e-5f);
        int row = n0 + r0 + j;
        if (row < n) {
            float4 o4;
            o4.x = d0 * rstd * g4.x + lb4.x;
            o4.y = d1 * rstd * g4.y + lb4.y;
            o4.z = d2 * rstd * g4.z + lb4.z;
            o4.w = d3 * rstd * g4.w + lb4.w;
            *(float4*)(O + (size_t)row * 64 + c0) = o4;
        }
    }
}

// ---------------------------------------------------------------------------
// gate = silu(x @ gw1 + gb1) @ gw2 + gb2    (one warp per node)
// ---------------------------------------------------------------------------
__global__ void __launch_bounds__(256) k_gate(
    const float* __restrict__ X,
    const float* __restrict__ GW1, const float* __restrict__ GB1,
    const float* __restrict__ GW2, const float* __restrict__ GB2,
    float* __restrict__ gate, int n) {
    __shared__ float sg[64 * 32];
    int tid = threadIdx.x;
    for (int i = tid; i < 64 * 32; i += 256) sg[i] = GW1[i];
    __syncthreads();
    int lane = tid & 31, w = tid >> 5;
    int node = blockIdx.x * 8 + w;
    if (node >= n) return;
    float t = GB1[lane];
    const float* xr = X + (size_t)node * 64;
    #pragma unroll
    for (int k = 0; k < 64; k++) t += xr[k] * sg[k * 32 + lane];
    float sil = t / (1.f + __expf(-t));
    float v = sil * GW2[lane];
    #pragma unroll
    for (int o = 16; o > 0; o >>= 1) v += __shfl_xor_sync(0xffffffffu, v, o);
    if (lane == 0) gate[node] = v + GB2[0];
}

// ---------------------------------------------------------------------------
// Per-graph softmax attention pool. batch sorted -> binary-search segment.
// ---------------------------------------------------------------------------
__global__ void k_pool(const float* __restrict__ X, const float* __restrict__ gate,
                       const int* __restrict__ batch, float* __restrict__ out, int n) {
    int g = blockIdx.x;
    int tid = threadIdx.x;  // 64 threads

    int lo = 0, hi = n;
    while (lo < hi) { int mid = (lo + hi) >> 1; if (batch[mid] < g) lo = mid + 1; else hi = mid; }
    int start = lo;
    lo = start; hi = n;
    while (lo < hi) { int mid = (lo + hi) >> 1; if (batch[mid] < g + 1) lo = mid + 1; else hi = mid; }
    int end = lo;

    if (start >= end) { out[(size_t)g * 64 + tid] = 0.f; return; }

    __shared__ float wred[2];
    float m = -3.402823e38f;
    for (int i = start + tid; i < end; i += 64) m = fmaxf(m, gate[i]);
    #pragma unroll
    for (int o = 16; o > 0; o >>= 1) m = fmaxf(m, __shfl_xor_sync(0xffffffffu, m, o));
    if ((tid & 31) == 0) wred[tid >> 5] = m;
    __syncthreads();
    m = fmaxf(wred[0], wred[1]);
    __syncthreads();
    float s = 0.f;
    for (int i = start + tid; i < end; i += 64) s += __expf(gate[i] - m);
    #pragma unroll
    for (int o = 16; o > 0; o >>= 1) s += __shfl_xor_sync(0xffffffffu, s, o);
    if ((tid & 31) == 0) wred[tid >> 5] = s;
    __syncthreads();
    float inv = 1.f / (wred[0] + wred[1]);

    float acc = 0.f;
    for (int i = start; i < end; i++) {
        float w = __expf(gate[i] - m);
        acc += w * X[(size_t)i * 64 + tid];
    }
    out[(size_t)g * 64 + tid] = acc * inv;
}

// ---------------------------------------------------------------------------
extern "C" void kernel_launch(void* const* d_in, const int* in_sizes, int n_in,
                              void* d_out, int out_size) {
    const float* x   = (const float*)d_in[0];
    const int*   ei  = (const int*)d_in[1];
    const int*   bat = (const int*)d_in[2];
    const float* W1  = (const float*)d_in[3];
    const float* b1  = (const float*)d_in[4];
    const float* W2  = (const float*)d_in[5];
    const float* b2  = (const float*)d_in[6];
    const float* eps = (const float*)d_in[7];
    const float* lng = (const float*)d_in[8];
    const float* lnb = (const float*)d_in[9];
    const float* gw1 = (const float*)d_in[10];
    const float* gb1 = (const float*)d_in[11];
    const float* gw2 = (const float*)d_in[12];
    const float* gb2 = (const float*)d_in[13];
    float* out = (float*)d_out;

    int n = in_sizes[0] / DDIM;
    int e = in_sizes[1] / 2;
    int g = out_size / DDIM;
    const int* src = ei;
    const int* dst = ei + e;

    float *ga, *gb, *ggate;
    int *deg, *rsa, *cur, *csr;
    cudaGetSymbolAddress((void**)&ga, g_a);
    cudaGetSymbolAddress((void**)&gb, g_b);
    cudaGetSymbolAddress((void**)&ggate, g_gate);
    cudaGetSymbolAddress((void**)&deg, g_deg);
    cudaGetSymbolAddress((void**)&rsa, g_rs);
    cudaGetSymbolAddress((void**)&cur, g_cur);
    cudaGetSymbolAddress((void**)&csr, g_csr);

    // CSR build (once per launch; reused for all 3 layers)
    k_zero<<<(n + 255) / 256, 256>>>(deg, n);
    k_hist<<<(e + 255) / 256, 256>>>(dst, deg, e);
    k_alloc<<<(n + 255) / 256, 256>>>(deg, rsa, cur, n);
    k_fill<<<(e + 255) / 256, 256>>>(src, dst, cur, csr, e);

    // 3 GIN layers, ping-pong buffers (gather reads whole graph -> no in-place)
    const float* in0 = x;  float* out0 = ga;
    int nblk = (n + 63) / 64;
    for (int l = 0; l < 3; l++) {
        k_mlp<<<nblk, 256>>>(in0, deg, rsa, csr, eps, l,
                             W1 + l * 4096, b1 + l * 64,
                             W2 + l * 4096, b2 + l * 64,
                             lng + l * 64, lnb + l * 64, out0, n);
        const float* nin = out0;
        out0 = (out0 == ga) ? gb : ga;
        in0 = nin;
    }
    const float* xf = in0;  // final features

    k_gate<<<(n + 7) / 8, 256>>>(xf, gw1, gb1, gw2, gb2, ggate, n);
    k_pool<<<g, 64>>>(xf, ggate, bat, out, n);
}